// round 3
// baseline (speedup 1.0000x reference)
#include <cuda_runtime.h>
#include <cstdint>

#define B_ 4
#define S_ 2048
#define D_ 1024
#define O_ 1024
#define E_ 16
#define K_ 512

// ---------------- device scratch (static, allocation-free) ----------------
__device__ __align__(16) float g_x32[B_ * S_ * D_];   // tf32-rounded x   (33.5 MB)
__device__ __align__(16) float g_w32[E_ * D_ * O_];   // tf32-rounded w   (67 MB)
__device__ float g_logits[B_ * E_ * S_];              // [b][e][s]
__device__ int   g_selidx[B_ * E_ * K_];
__device__ float g_selscale[B_ * E_ * K_];

// ---------------- helpers ----------------
__device__ __forceinline__ float to_tf32(float f) {
    uint32_t u;
    asm("cvt.rna.tf32.f32 %0, %1;" : "=r"(u) : "f"(f));
    return __uint_as_float(u);
}

// ---------------- kernel 1: round x and w to tf32 (unbiased) ----------------
__global__ void cvt_kernel(const float4* __restrict__ x, const float4* __restrict__ w) {
    const int NX = B_ * S_ * D_ / 4;
    const int NW = E_ * D_ * O_ / 4;
    int i = blockIdx.x * blockDim.x + threadIdx.x;
    if (i < NX) {
        float4 v = x[i];
        v.x = to_tf32(v.x); v.y = to_tf32(v.y); v.z = to_tf32(v.z); v.w = to_tf32(v.w);
        reinterpret_cast<float4*>(g_x32)[i] = v;
    } else if (i < NX + NW) {
        int j = i - NX;
        float4 v = w[j];
        v.x = to_tf32(v.x); v.y = to_tf32(v.y); v.z = to_tf32(v.z); v.w = to_tf32(v.w);
        reinterpret_cast<float4*>(g_w32)[j] = v;
    }
}

// ---------------- kernel 2: gate logits [B,S,E] -> stored [B,E,S] ----------------
// one warp per token; gate_w transposed in dynamic smem [E][D].
// Kahan-compensated accumulation (rn intrinsics so fast-math can't strip it):
// the top-k boundary gap is ~1.5e-3 in logit units; naive 32-term serial fp32
// accumulation noise (~3e-6) risks selecting a different token than the
// reference, which corrupts two whole output rows (~2% L2 error -> fail).
__global__ void gate_kernel(const float* __restrict__ x,
                            const float* __restrict__ gw,
                            const float* __restrict__ gb) {
    extern __shared__ float sgw[];  // 16*1024 floats = 64 KB
    const int tid = threadIdx.x;
    for (int i = tid; i < D_ * E_; i += 256) {
        int d = i >> 4, e = i & 15;          // gw is [D][E]
        sgw[e * D_ + d] = gw[i];
    }
    __syncthreads();

    const int warp = tid >> 5, lane = tid & 31;
    const int t = blockIdx.x * 8 + warp;      // global token id 0..8191
    const float* xr = x + (size_t)t * D_;

    float acc[E_], comp[E_];
#pragma unroll
    for (int e = 0; e < E_; ++e) { acc[e] = 0.f; comp[e] = 0.f; }

    for (int d = lane; d < D_; d += 32) {
        float xv = xr[d];
#pragma unroll
        for (int e = 0; e < E_; ++e) {
            float y = __fsub_rn(__fmul_rn(xv, sgw[e * D_ + d]), comp[e]);
            float tt = __fadd_rn(acc[e], y);
            comp[e] = __fsub_rn(__fsub_rn(tt, acc[e]), y);
            acc[e] = tt;
        }
    }

    float myv = 0.f;
#pragma unroll
    for (int e = 0; e < E_; ++e) {
        float v = acc[e];
#pragma unroll
        for (int o = 16; o; o >>= 1) v += __shfl_xor_sync(0xffffffffu, v, o);
        if (lane == e) myv = v;
    }
    if (lane < E_) {
        int b = t >> 11, s = t & (S_ - 1);
        g_logits[((size_t)(b * E_ + lane)) * S_ + s] = myv + gb[lane];
    }
}

// ---------------- kernel 3: softmax over tokens + exact top-512 select ----------------
// one block per (b,e). Radix-select on float bits; tie-break = lowest index (matches lax.top_k).
__global__ void topk_kernel() {
    __shared__ float sredf[8];
    __shared__ int   sredi[8];
    __shared__ float s_bf;
    __shared__ int   s_bi;
    __shared__ int   s_ctr;
    __shared__ int   s_wcnt[8];

    const int tid = threadIdx.x;
    const int lane = tid & 31, wid = tid >> 5;
    const int be = blockIdx.x;
    const float* L = g_logits + (size_t)be * S_;

    float vloc[8];
    float lmax = -3.0e38f;
#pragma unroll
    for (int j = 0; j < 8; ++j) {
        float v = L[tid + j * 256];
        vloc[j] = v;
        lmax = fmaxf(lmax, v);
    }
#pragma unroll
    for (int o = 16; o; o >>= 1) lmax = fmaxf(lmax, __shfl_xor_sync(0xffffffffu, lmax, o));
    if (lane == 0) sredf[wid] = lmax;
    __syncthreads();
    if (tid == 0) {
        float m = sredf[0];
        for (int i = 1; i < 8; ++i) m = fmaxf(m, sredf[i]);
        s_bf = m;
    }
    __syncthreads();
    const float m = s_bf;
    __syncthreads();

    float lsum = 0.f;
#pragma unroll
    for (int j = 0; j < 8; ++j) {
        float ex = expf(vloc[j] - m);
        vloc[j] = ex;
        lsum += ex;
    }
#pragma unroll
    for (int o = 16; o; o >>= 1) lsum += __shfl_xor_sync(0xffffffffu, lsum, o);
    if (lane == 0) sredf[wid] = lsum;
    __syncthreads();
    if (tid == 0) {
        float t = 0.f;
        for (int i = 0; i < 8; ++i) t += sredf[i];
        s_bf = t;
    }
    __syncthreads();
    const float inv = 1.0f / s_bf;

    unsigned pv[8];
#pragma unroll
    for (int j = 0; j < 8; ++j) pv[j] = __float_as_uint(vloc[j] * inv);  // probs > 0

    // radix-select: prefix ends as bit pattern of the K-th largest prob
    unsigned prefix = 0u;
    for (int bit = 30; bit >= 0; --bit) {
        unsigned cand = prefix | (1u << bit);
        int c = 0;
#pragma unroll
        for (int j = 0; j < 8; ++j) c += (pv[j] >= cand) ? 1 : 0;
#pragma unroll
        for (int o = 16; o; o >>= 1) c += __shfl_xor_sync(0xffffffffu, c, o);
        if (lane == 0) sredi[wid] = c;
        __syncthreads();
        if (tid == 0) {
            int t = 0;
            for (int i = 0; i < 8; ++i) t += sredi[i];
            s_bi = t;
        }
        __syncthreads();
        if (s_bi >= K_) prefix = cand;
        __syncthreads();
    }

    // strictly-greater elements (order in list irrelevant for scatter)
    if (tid == 0) s_ctr = 0;
    __syncthreads();
#pragma unroll
    for (int j = 0; j < 8; ++j) {
        if (pv[j] > prefix) {
            int pos = atomicAdd(&s_ctr, 1);
            g_selidx[be * K_ + pos] = tid + j * 256;
            g_selscale[be * K_ + pos] = 1.0f / __uint_as_float(pv[j]);
        }
    }
    __syncthreads();
    const int G = s_ctr;
    const int T = K_ - G;

    // elements equal to threshold: take lowest token indices first (jax tie-break)
    int taken = 0;
    for (int j = 0; j < 8; ++j) {
        bool eq = (pv[j] == prefix);
        unsigned mask = __ballot_sync(0xffffffffu, eq);
        if (lane == 0) s_wcnt[wid] = __popc(mask);
        __syncthreads();
        int woff = 0, tot = 0;
#pragma unroll
        for (int w2 = 0; w2 < 8; ++w2) {
            int cc = s_wcnt[w2];
            if (w2 < wid) woff += cc;
            tot += cc;
        }
        int rank = taken + woff + __popc(mask & ((1u << lane) - 1));
        if (eq && rank < T) {
            int pos = G + rank;
            g_selidx[be * K_ + pos] = tid + j * 256;
            g_selscale[be * K_ + pos] = 1.0f / __uint_as_float(pv[j]);
        }
        taken += tot;
        __syncthreads();
    }
}

// ---------------- kernel 4: gather-GEMM (tf32 mma) + staged vector scatter-add ----------------
// per (b,e): C[512,1024] = gathered_x[512,1024] @ w[e][1024,1024]
// block tile 128x128x32, 8 warps (4M x 2N), warp tile 32x64, mma m16n8k8 tf32
// Epilogue: stage scaled C tile in smem (reusing operand buffers), then
// red.global.add.v4.f32 -> 4x fewer LSU lanes than scalar atomics, coalesced 16B.
__global__ void __launch_bounds__(256)
moe_gemm_kernel(const float* __restrict__ bias, float* __restrict__ out) {
    extern __shared__ float smem[];
    float* As = smem;                       // 2 * 128*36   = 9216 floats
    float* Bs = smem + 2 * 4608;            // 2 * 32*136   = 8704 floats
    float* s_scale = smem + 2 * 4608 + 2 * 4352;  // 128 floats
    int*   s_tok   = (int*)(s_scale + 128);       // 128 ints

    const int tid = threadIdx.x;
    const int be = blockIdx.z;
    const int b = be >> 4, e = be & 15;
    const int m0 = blockIdx.y * 128;
    const int n0 = blockIdx.x * 128;

    if (tid < 128) {
        s_tok[tid]   = g_selidx[be * K_ + m0 + tid];
        s_scale[tid] = g_selscale[be * K_ + m0 + tid];
    }
    __syncthreads();

    // per-thread loader setup (4 x 16B chunks each for A and B per k-tile)
    const float* aptr[4];
    const float* bptr[4];
    int adst[4], bdst[4];
#pragma unroll
    for (int i = 0; i < 4; ++i) {
        int id = tid + i * 256;
        int ar = id >> 3, akq = id & 7;                 // A: row 0..127, k-quad 0..7
        aptr[i] = g_x32 + ((size_t)(b * S_ + s_tok[ar])) * D_ + akq * 4;
        adst[i] = ar * 36 + akq * 4;
        int bk = id >> 5, bnq = id & 31;                // B: k 0..31, n-quad 0..31
        bptr[i] = g_w32 + (size_t)e * D_ * O_ + (size_t)bk * O_ + n0 + bnq * 4;
        bdst[i] = bk * 136 + bnq * 4;
    }

    auto issue = [&](int kt, int buf) {
        float* Ad = As + buf * 4608;
        float* Bd = Bs + buf * 4352;
#pragma unroll
        for (int i = 0; i < 4; ++i) {
            uint32_t sa = (uint32_t)__cvta_generic_to_shared(Ad + adst[i]);
            asm volatile("cp.async.cg.shared.global [%0], [%1], 16;\n"
                         :: "r"(sa), "l"(aptr[i] + kt * 32));
        }
#pragma unroll
        for (int i = 0; i < 4; ++i) {
            uint32_t sb = (uint32_t)__cvta_generic_to_shared(Bd + bdst[i]);
            asm volatile("cp.async.cg.shared.global [%0], [%1], 16;\n"
                         :: "r"(sb), "l"(bptr[i] + (size_t)kt * 32 * O_));
        }
        asm volatile("cp.async.commit_group;\n");
    };

    float acc[2][8][4];
#pragma unroll
    for (int mt = 0; mt < 2; ++mt)
#pragma unroll
        for (int nt = 0; nt < 8; ++nt)
#pragma unroll
            for (int r = 0; r < 4; ++r) acc[mt][nt][r] = 0.f;

    const int warp = tid >> 5, lane = tid & 31;
    const int wm = warp & 3, wn = warp >> 2;   // 4 M-warps x 2 N-warps
    const int gid = lane >> 2, tig = lane & 3;

    issue(0, 0);
#pragma unroll 1
    for (int kt = 0; kt < 32; ++kt) {
        const int cbuf = kt & 1;
        if (kt + 1 < 32) {
            issue(kt + 1, cbuf ^ 1);
            asm volatile("cp.async.wait_group 1;\n");
        } else {
            asm volatile("cp.async.wait_group 0;\n");
        }
        __syncthreads();

        const uint32_t* Au = reinterpret_cast<const uint32_t*>(As + cbuf * 4608);
        const uint32_t* Bu = reinterpret_cast<const uint32_t*>(Bs + cbuf * 4352);

#pragma unroll
        for (int ks = 0; ks < 4; ++ks) {
            const int kb = ks * 8;
            uint32_t a[2][4];
#pragma unroll
            for (int mt = 0; mt < 2; ++mt) {
                int r = wm * 32 + mt * 16 + gid;
                int c = kb + tig;
                a[mt][0] = Au[r * 36 + c];
                a[mt][1] = Au[(r + 8) * 36 + c];
                a[mt][2] = Au[r * 36 + c + 4];
                a[mt][3] = Au[(r + 8) * 36 + c + 4];
            }
            uint32_t bb[8][2];
#pragma unroll
            for (int nt = 0; nt < 8; ++nt) {
                int nc = wn * 64 + nt * 8 + gid;
                int kr = kb + tig;
                bb[nt][0] = Bu[kr * 136 + nc];
                bb[nt][1] = Bu[(kr + 4) * 136 + nc];
            }
#pragma unroll
            for (int mt = 0; mt < 2; ++mt)
#pragma unroll
                for (int nt = 0; nt < 8; ++nt)
                    asm volatile(
                        "mma.sync.aligned.m16n8k8.row.col.f32.tf32.tf32.f32 "
                        "{%0,%1,%2,%3}, {%4,%5,%6,%7}, {%8,%9}, {%0,%1,%2,%3};\n"
                        : "+f"(acc[mt][nt][0]), "+f"(acc[mt][nt][1]),
                          "+f"(acc[mt][nt][2]), "+f"(acc[mt][nt][3])
                        : "r"(a[mt][0]), "r"(a[mt][1]), "r"(a[mt][2]), "r"(a[mt][3]),
                          "r"(bb[nt][0]), "r"(bb[nt][1]));
        }
        __syncthreads();
    }

    // ---- epilogue: stage (acc + bias_e) * (1/prob) into smem, then vector red ----
    // Reuse operand smem: Cs needs 128 rows x 136 stride = 17408 floats <= 17920.
    float* Cs = smem;
    const float bv = bias[e];
#pragma unroll
    for (int mt = 0; mt < 2; ++mt) {
#pragma unroll
        for (int h = 0; h < 2; ++h) {
            int rl = wm * 32 + mt * 16 + gid + h * 8;
            float sc = s_scale[rl];
#pragma unroll
            for (int nt = 0; nt < 8; ++nt) {
                int col = wn * 64 + nt * 8 + tig * 2;
                Cs[rl * 136 + col]     = (acc[mt][nt][h * 2 + 0] + bv) * sc;
                Cs[rl * 136 + col + 1] = (acc[mt][nt][h * 2 + 1] + bv) * sc;
            }
        }
    }
    __syncthreads();

#pragma unroll
    for (int i = 0; i < 16; ++i) {
        int id = tid + i * 256;          // 4096 float4 chunks: 128 rows x 32 chunks
        int r = id >> 5, c4 = (id & 31) * 4;
        float4 v = *reinterpret_cast<const float4*>(Cs + r * 136 + c4);
        float* dst = out + ((size_t)(b * S_ + s_tok[r])) * O_ + n0 + c4;
        asm volatile("red.global.add.v4.f32 [%0], {%1,%2,%3,%4};\n"
                     :: "l"(dst), "f"(v.x), "f"(v.y), "f"(v.z), "f"(v.w)
                     : "memory");
    }
}

// ---------------- launch ----------------
extern "C" void kernel_launch(void* const* d_in, const int* in_sizes, int n_in,
                              void* d_out, int out_size) {
    const float* x    = (const float*)d_in[0];
    const float* gw   = (const float*)d_in[1];
    const float* gb   = (const float*)d_in[2];
    const float* w    = (const float*)d_in[3];
    const float* bias = (const float*)d_in[4];
    float* out = (float*)d_out;

    cudaFuncSetAttribute(gate_kernel, cudaFuncAttributeMaxDynamicSharedMemorySize, 65536);
    cudaFuncSetAttribute(moe_gemm_kernel, cudaFuncAttributeMaxDynamicSharedMemorySize, 72704);

    cudaMemsetAsync(d_out, 0, (size_t)out_size * sizeof(float), 0);

    const int total4 = (B_ * S_ * D_ + E_ * D_ * O_) / 4;
    cvt_kernel<<<(total4 + 255) / 256, 256>>>((const float4*)x, (const float4*)w);

    gate_kernel<<<(B_ * S_) / 8, 256, 65536>>>(x, gw, gb);

    topk_kernel<<<B_ * E_, 256>>>();

    dim3 g(O_ / 128, K_ / 128, B_ * E_);   // (8, 4, 64)
    moe_gemm_kernel<<<g, 256, 72704>>>(bias, out);
}

// round 13
// speedup vs baseline: 1.0103x; 1.0103x over previous
#include <cuda_runtime.h>
#include <cstdint>

#define B_ 4
#define S_ 2048
#define D_ 1024
#define O_ 1024
#define E_ 16
#define K_ 512

// ---------------- device scratch (static, allocation-free) ----------------
__device__ __align__(16) float g_x32[B_ * S_ * D_];   // tf32-rounded x   (33.5 MB)
__device__ __align__(16) float g_w32[E_ * D_ * O_];   // tf32-rounded w   (67 MB)
__device__ float g_logits[B_ * E_ * S_];              // [b][e][s]
__device__ int   g_selidx[B_ * E_ * K_];
__device__ float g_selscale[B_ * E_ * K_];

// ---------------- helpers ----------------
__device__ __forceinline__ float to_tf32(float f) {
    uint32_t u;
    asm("cvt.rna.tf32.f32 %0, %1;" : "=r"(u) : "f"(f));
    return __uint_as_float(u);
}

// ---------------- kernel 1: round w to tf32 (unbiased) ----------------
__global__ void cvt_w_kernel(const float4* __restrict__ w) {
    int i = blockIdx.x * blockDim.x + threadIdx.x;
    float4 v = w[i];
    v.x = to_tf32(v.x); v.y = to_tf32(v.y); v.z = to_tf32(v.z); v.w = to_tf32(v.w);
    reinterpret_cast<float4*>(g_w32)[i] = v;
}

// ---------------- kernel 2: gate logits (Kahan) + fused x->tf32 rounding ----------------
__global__ void gate_kernel(const float* __restrict__ x,
                            const float* __restrict__ gw,
                            const float* __restrict__ gb) {
    extern __shared__ float sgw[];  // 16*1024 floats = 64 KB
    const int tid = threadIdx.x;
    for (int i = tid; i < D_ * E_; i += 256) {
        int d = i >> 4, e = i & 15;          // gw is [D][E]
        sgw[e * D_ + d] = gw[i];
    }
    __syncthreads();

    const int warp = tid >> 5, lane = tid & 31;
    const int t = blockIdx.x * 8 + warp;      // global token id 0..8191
    const float* xr = x + (size_t)t * D_;
    float* xw = g_x32 + (size_t)t * D_;

    float acc[E_], comp[E_];
#pragma unroll
    for (int e = 0; e < E_; ++e) { acc[e] = 0.f; comp[e] = 0.f; }

    for (int d = lane; d < D_; d += 32) {
        float xv = xr[d];
        xw[d] = to_tf32(xv);                   // fused rounding store for the GEMM copy
#pragma unroll
        for (int e = 0; e < E_; ++e) {
            float y = __fsub_rn(__fmul_rn(xv, sgw[e * D_ + d]), comp[e]);
            float tt = __fadd_rn(acc[e], y);
            comp[e] = __fsub_rn(__fsub_rn(tt, acc[e]), y);
            acc[e] = tt;
        }
    }

    float myv = 0.f;
#pragma unroll
    for (int e = 0; e < E_; ++e) {
        float v = acc[e];
#pragma unroll
        for (int o = 16; o; o >>= 1) v += __shfl_xor_sync(0xffffffffu, v, o);
        if (lane == e) myv = v;
    }
    if (lane < E_) {
        int b = t >> 11, s = t & (S_ - 1);
        g_logits[((size_t)(b * E_ + lane)) * S_ + s] = myv + gb[lane];
    }
}

// ---------------- kernel 3: softmax over tokens + exact top-512 ----------------
__global__ void topk_kernel() {
    __shared__ float sredf[8];
    __shared__ int   sredi[8];
    __shared__ float s_bf;
    __shared__ int   s_bi;
    __shared__ int   s_ctr;
    __shared__ int   s_wcnt[8];

    const int tid = threadIdx.x;
    const int lane = tid & 31, wid = tid >> 5;
    const int be = blockIdx.x;
    const float* L = g_logits + (size_t)be * S_;

    float vloc[8];
    float lmax = -3.0e38f;
#pragma unroll
    for (int j = 0; j < 8; ++j) {
        float v = L[tid + j * 256];
        vloc[j] = v;
        lmax = fmaxf(lmax, v);
    }
#pragma unroll
    for (int o = 16; o; o >>= 1) lmax = fmaxf(lmax, __shfl_xor_sync(0xffffffffu, lmax, o));
    if (lane == 0) sredf[wid] = lmax;
    __syncthreads();
    if (tid == 0) {
        float m = sredf[0];
        for (int i = 1; i < 8; ++i) m = fmaxf(m, sredf[i]);
        s_bf = m;
    }
    __syncthreads();
    const float m = s_bf;
    __syncthreads();

    float lsum = 0.f;
#pragma unroll
    for (int j = 0; j < 8; ++j) {
        float ex = expf(vloc[j] - m);
        vloc[j] = ex;
        lsum += ex;
    }
#pragma unroll
    for (int o = 16; o; o >>= 1) lsum += __shfl_xor_sync(0xffffffffu, lsum, o);
    if (lane == 0) sredf[wid] = lsum;
    __syncthreads();
    if (tid == 0) {
        float t = 0.f;
        for (int i = 0; i < 8; ++i) t += sredf[i];
        s_bf = t;
    }
    __syncthreads();
    const float inv = 1.0f / s_bf;

    unsigned pv[8];
#pragma unroll
    for (int j = 0; j < 8; ++j) pv[j] = __float_as_uint(vloc[j] * inv);

    unsigned prefix = 0u;
    for (int bit = 30; bit >= 0; --bit) {
        unsigned cand = prefix | (1u << bit);
        int c = 0;
#pragma unroll
        for (int j = 0; j < 8; ++j) c += (pv[j] >= cand) ? 1 : 0;
#pragma unroll
        for (int o = 16; o; o >>= 1) c += __shfl_xor_sync(0xffffffffu, c, o);
        if (lane == 0) sredi[wid] = c;
        __syncthreads();
        if (tid == 0) {
            int t = 0;
            for (int i = 0; i < 8; ++i) t += sredi[i];
            s_bi = t;
        }
        __syncthreads();
        if (s_bi >= K_) prefix = cand;
        __syncthreads();
    }

    if (tid == 0) s_ctr = 0;
    __syncthreads();
#pragma unroll
    for (int j = 0; j < 8; ++j) {
        if (pv[j] > prefix) {
            int pos = atomicAdd(&s_ctr, 1);
            g_selidx[be * K_ + pos] = tid + j * 256;
            g_selscale[be * K_ + pos] = 1.0f / __uint_as_float(pv[j]);
        }
    }
    __syncthreads();
    const int G = s_ctr;
    const int T = K_ - G;

    int taken = 0;
    for (int j = 0; j < 8; ++j) {
        bool eq = (pv[j] == prefix);
        unsigned mask = __ballot_sync(0xffffffffu, eq);
        if (lane == 0) s_wcnt[wid] = __popc(mask);
        __syncthreads();
        int woff = 0, tot = 0;
#pragma unroll
        for (int w2 = 0; w2 < 8; ++w2) {
            int cc = s_wcnt[w2];
            if (w2 < wid) woff += cc;
            tot += cc;
        }
        int rank = taken + woff + __popc(mask & ((1u << lane) - 1));
        if (eq && rank < T) {
            int pos = G + rank;
            g_selidx[be * K_ + pos] = tid + j * 256;
            g_selscale[be * K_ + pos] = 1.0f / __uint_as_float(pv[j]);
        }
        taken += tot;
        __syncthreads();
    }
}

// ---------------- kernel 4: gather-GEMM (tf32 mma), 3-stage pipeline, 1 sync/k-tile ----------
// per (b,e): C[512,1024] = gathered_x[512,1024] @ w[e][1024,1024]
// block tile 128x128x32, 8 warps (4M x 2N), warp tile 32x64, mma m16n8k8 tf32.
// CUTLASS multistage order per k-tile: wait_group 1 -> __syncthreads -> issue kt+2 -> mma kt.
// The single sync doubles as the write-hazard guard for buffer (kt-1)%3.
// Epilogue: stage scaled C in smem (stages 0-1 region), red.global.add.v4.f32.
#define STG_FLOATS 8960                      // A 128*36 + B 32*136
#define NSTG 3
#define SMEM_FLOATS (NSTG * STG_FLOATS + 256)

__global__ void __launch_bounds__(256)
moe_gemm_kernel(const float* __restrict__ bias, float* __restrict__ out) {
    extern __shared__ float smem[];
    float* s_scale = smem + NSTG * STG_FLOATS;       // 128 floats
    int*   s_tok   = (int*)(s_scale + 128);          // 128 ints

    const int tid = threadIdx.x;
    const int be = blockIdx.z;
    const int b = be >> 4, e = be & 15;
    const int m0 = blockIdx.y * 128;
    const int n0 = blockIdx.x * 128;

    if (tid < 128) {
        s_tok[tid]   = g_selidx[be * K_ + m0 + tid];
        s_scale[tid] = g_selscale[be * K_ + m0 + tid];
    }
    __syncthreads();

    // per-thread loader setup (4 x 16B chunks for A, 4 for B, per k-tile)
    const float* aptr[4];
    const float* bptr[4];
    int adst[4], bdst[4];
#pragma unroll
    for (int i = 0; i < 4; ++i) {
        int id = tid + i * 256;
        int ar = id >> 3, akq = id & 7;                 // A: row 0..127, k-quad 0..7
        aptr[i] = g_x32 + ((size_t)(b * S_ + s_tok[ar])) * D_ + akq * 4;
        adst[i] = ar * 36 + akq * 4;
        int bk = id >> 5, bnq = id & 31;                // B: k 0..31, n-quad 0..31
        bptr[i] = g_w32 + (size_t)e * D_ * O_ + (size_t)bk * O_ + n0 + bnq * 4;
        bdst[i] = 4608 + bk * 136 + bnq * 4;
    }

    auto issue = [&](int kt, int stg) {
        float* Sd = smem + stg * STG_FLOATS;
#pragma unroll
        for (int i = 0; i < 4; ++i) {
            uint32_t sa = (uint32_t)__cvta_generic_to_shared(Sd + adst[i]);
            asm volatile("cp.async.cg.shared.global [%0], [%1], 16;\n"
                         :: "r"(sa), "l"(aptr[i] + kt * 32));
        }
#pragma unroll
        for (int i = 0; i < 4; ++i) {
            uint32_t sb = (uint32_t)__cvta_generic_to_shared(Sd + bdst[i]);
            asm volatile("cp.async.cg.shared.global [%0], [%1], 16;\n"
                         :: "r"(sb), "l"(bptr[i] + (size_t)kt * 32 * O_));
        }
        asm volatile("cp.async.commit_group;\n");
    };

    float acc[2][8][4];
#pragma unroll
    for (int mt = 0; mt < 2; ++mt)
#pragma unroll
        for (int nt = 0; nt < 8; ++nt)
#pragma unroll
            for (int r = 0; r < 4; ++r) acc[mt][nt][r] = 0.f;

    const int warp = tid >> 5, lane = tid & 31;
    const int wm = warp & 3, wn = warp >> 2;   // 4 M-warps x 2 N-warps
    const int gid = lane >> 2, tig = lane & 3;

    issue(0, 0);
    issue(1, 1);

    int stg = 0;
#pragma unroll 1
    for (int kt = 0; kt < 32; ++kt) {
        if (kt < 31) {
            asm volatile("cp.async.wait_group 1;\n");
        } else {
            asm volatile("cp.async.wait_group 0;\n");
        }
        __syncthreads();   // kt data visible to all; all warps past mma kt-1

        if (kt + 2 < 32) {
            int nstg = stg + 2;
            if (nstg >= NSTG) nstg -= NSTG;
            issue(kt + 2, nstg);   // overwrites stage (kt-1)%3: safe after sync
        }

        const uint32_t* Au = reinterpret_cast<const uint32_t*>(smem + stg * STG_FLOATS);
        const uint32_t* Bu = Au + 4608;

#pragma unroll
        for (int ks = 0; ks < 4; ++ks) {
            const int kb = ks * 8;
            uint32_t a[2][4];
#pragma unroll
            for (int mt = 0; mt < 2; ++mt) {
                int r = wm * 32 + mt * 16 + gid;
                int c = kb + tig;
                a[mt][0] = Au[r * 36 + c];
                a[mt][1] = Au[(r + 8) * 36 + c];
                a[mt][2] = Au[r * 36 + c + 4];
                a[mt][3] = Au[(r + 8) * 36 + c + 4];
            }
            uint32_t bb[8][2];
#pragma unroll
            for (int nt = 0; nt < 8; ++nt) {
                int nc = wn * 64 + nt * 8 + gid;
                int kr = kb + tig;
                bb[nt][0] = Bu[kr * 136 + nc];
                bb[nt][1] = Bu[(kr + 4) * 136 + nc];
            }
#pragma unroll
            for (int mt = 0; mt < 2; ++mt)
#pragma unroll
                for (int nt = 0; nt < 8; ++nt)
                    asm volatile(
                        "mma.sync.aligned.m16n8k8.row.col.f32.tf32.tf32.f32 "
                        "{%0,%1,%2,%3}, {%4,%5,%6,%7}, {%8,%9}, {%0,%1,%2,%3};\n"
                        : "+f"(acc[mt][nt][0]), "+f"(acc[mt][nt][1]),
                          "+f"(acc[mt][nt][2]), "+f"(acc[mt][nt][3])
                        : "r"(a[mt][0]), "r"(a[mt][1]), "r"(a[mt][2]), "r"(a[mt][3]),
                          "r"(bb[nt][0]), "r"(bb[nt][1]));
        }

        if (++stg == NSTG) stg = 0;
    }

    // ---- epilogue: stage (acc + bias_e) * (1/prob) into smem, then vector red ----
    __syncthreads();   // all warps done with mma before Cs overwrites stage smem
    float* Cs = smem;  // 128 rows x 136 stride = 17408 floats (< 2 stages = 17920)
    const float bv = bias[e];
#pragma unroll
    for (int mt = 0; mt < 2; ++mt) {
#pragma unroll
        for (int h = 0; h < 2; ++h) {
            int rl = wm * 32 + mt * 16 + gid + h * 8;
            float sc = s_scale[rl];
#pragma unroll
            for (int nt = 0; nt < 8; ++nt) {
                int col = wn * 64 + nt * 8 + tig * 2;
                Cs[rl * 136 + col]     = (acc[mt][nt][h * 2 + 0] + bv) * sc;
                Cs[rl * 136 + col + 1] = (acc[mt][nt][h * 2 + 1] + bv) * sc;
            }
        }
    }
    __syncthreads();

#pragma unroll
    for (int i = 0; i < 16; ++i) {
        int id = tid + i * 256;          // 4096 float4 chunks: 128 rows x 32 chunks
        int r = id >> 5, c4 = (id & 31) * 4;
        float4 v = *reinterpret_cast<const float4*>(Cs + r * 136 + c4);
        float* dst = out + ((size_t)(b * S_ + s_tok[r])) * O_ + n0 + c4;
        asm volatile("red.global.add.v4.f32 [%0], {%1,%2,%3,%4};\n"
                     :: "l"(dst), "f"(v.x), "f"(v.y), "f"(v.z), "f"(v.w)
                     : "memory");
    }
}

// ---------------- launch ----------------
extern "C" void kernel_launch(void* const* d_in, const int* in_sizes, int n_in,
                              void* d_out, int out_size) {
    const float* x    = (const float*)d_in[0];
    const float* gw   = (const float*)d_in[1];
    const float* gb   = (const float*)d_in[2];
    const float* w    = (const float*)d_in[3];
    const float* bias = (const float*)d_in[4];
    float* out = (float*)d_out;

    cudaFuncSetAttribute(gate_kernel, cudaFuncAttributeMaxDynamicSharedMemorySize, 65536);
    cudaFuncSetAttribute(moe_gemm_kernel, cudaFuncAttributeMaxDynamicSharedMemorySize,
                         SMEM_FLOATS * 4);

    cudaMemsetAsync(d_out, 0, (size_t)out_size * sizeof(float), 0);

    gate_kernel<<<(B_ * S_) / 8, 256, 65536>>>(x, gw, gb);   // also writes g_x32 (tf32)

    cvt_w_kernel<<<(E_ * D_ * O_ / 4) / 256, 256>>>((const float4*)w);

    topk_kernel<<<B_ * E_, 256>>>();

    dim3 g(O_ / 128, K_ / 128, B_ * E_);   // (8, 4, 64)
    moe_gemm_kernel<<<g, 256, SMEM_FLOATS * 4>>>(bias, out);
}